// round 11
// baseline (speedup 1.0000x reference)
#include <cuda_runtime.h>

#define N_POS   1024
#define BDIM    256
#define SPLIT   8
#define NBLK    (64 * SPLIT)   // 512
#define KTOP    10
#define NWARP   (BDIM / 32)    // 8
#define CHUNK   128            // compile-time j-chunk: SPLIT*CHUNK == N_POS
#define TRIPS   (CHUNK / 2)    // 64 float4 loads (2 j's each) — constant!

__device__ float    g_partial[NBLK];
__device__ int      g_count[NBLK];
__device__ unsigned g_ticket;   // zero-init; reset to 0 by the last block each launch

__constant__ float c_idcg[11] = {
    0.0f, 1.0f, 1.6309297535714574f, 2.1309297535714574f,
    2.5616063116448505f, 2.9484591188793920f, 3.3046663059874144f,
    3.6379996393207477f, 3.9534645161064764f, 4.2544945117704580f,
    4.5435593380883460f
};

__global__ __launch_bounds__(BDIM, 4) void lambdarank_fused(
    const float* __restrict__ scores, const int* __restrict__ rels,
    float* __restrict__ out)
{
    __shared__ float4 relSD4[N_POS / 2];   // (E, d) pairs, float4 view, zero-padded
    __shared__ float4 nonSD4[N_POS / 2];
    __shared__ int    sh_cntR[NWARP];
    __shared__ int    sh_baseR[NWARP], sh_baseN[NWARP];
    __shared__ int    sh_tot[2];
    __shared__ float  red_f[NWARP];
    __shared__ int    red_i[NWARP];
    __shared__ bool   s_last;

    float2* relSD = (float2*)relSD4;
    float2* nonSD = (float2*)nonSD4;

    const int b    = blockIdx.x >> 3;          // SPLIT = 8
    const int s    = blockIdx.x & (SPLIT - 1);
    const int t    = threadIdx.x;
    const int lane = t & 31;
    const int wid  = t >> 5;
    const unsigned lt_mask = (1u << lane) - 1u;

    // ---- Phase 1: cheap ballot count (all blocks) ----
    unsigned masks[4];
    float    sc[4];
    {
        int cr = 0;
        #pragma unroll
        for (int it = 0; it < 4; it++) {
            int p = (wid << 7) + (it << 5) + lane;
            sc[it] = scores[b * N_POS + p];
            int r  = rels[b * N_POS + p];
            unsigned m = __ballot_sync(0xffffffffu, r != 0);
            masks[it] = m;
            cr += __popc(m);
        }
        if (lane == 0) sh_cntR[wid] = cr;
    }
    __syncthreads();
    if (t == 0) {
        int aR = 0, aN = 0;
        #pragma unroll
        for (int w = 0; w < NWARP; w++) {
            sh_baseR[w] = aR; sh_baseN[w] = aN;
            aR += sh_cntR[w]; aN += 128 - sh_cntR[w];
        }
        sh_tot[0] = aR; sh_tot[1] = aN;
    }
    __syncthreads();

    const int nrel = sh_tot[0];
    const int nnon = sh_tot[1];
    const int j0   = s * CHUNK;

    // Block-uniform early out: this block's j-chunk is entirely beyond nnon,
    // or the batch has no valid pairs.
    const bool active = (j0 < nnon) && (nrel > 0);

    float thread_sum = 0.0f;
    int   blk_count  = 0;

    if (active) {
        // ---- Phase 2: scatter compaction (active blocks only) ----
        {
            int rb = sh_baseR[wid], nb = sh_baseN[wid];
            #pragma unroll
            for (int it = 0; it < 4; it++) {
                int p = (wid << 7) + (it << 5) + lane;
                unsigned m = masks[it];
                bool hit = (m >> lane) & 1u;
                float E  = __expf(hit ? -sc[it] : sc[it]);
                float d  = __fdividef(1.0f, __log2f((float)p + 2.0f));
                float2 v = make_float2(E, d);
                int preR = __popc(m & lt_mask);
                if (hit) relSD[rb + preR]          = v;
                else     nonSD[nb + (lane - preR)] = v;
                rb += __popc(m);
                nb += 32 - __popc(m);
            }
        }
        // Zero-fill tails: E=0 entries contribute exactly 0 in the pair loop
        for (int idx = nrel + t; idx < N_POS; idx += BDIM)
            relSD[idx] = make_float2(0.0f, 0.0f);
        for (int idx = nnon + t; idx < N_POS; idx += BDIM)
            nonSD[idx] = make_float2(0.0f, 0.0f);
        __syncthreads();

        const float idcg = c_idcg[(nrel < KTOP) ? nrel : KTOP];
        const float norm = 0.69314718055994531f / (idcg + 1e-8f);  // ln2/(idcg+eps)

        int cntj = nnon - j0;
        cntj = (cntj > CHUNK) ? CHUNK : cntj;
        blk_count = nrel * cntj;

        const float4* nj4 = (const float4*)&nonSD[j0];   // 16B-aligned (j0 even)

        // 2 i's per thread (i = ibase+2t, +1): all 8 warps active for nrel >= 64
        #pragma unroll
        for (int ibase = 0; ibase < N_POS; ibase += 2 * BDIM) {   // 2 passes
            if (ibase >= nrel) break;
            if (ibase + (wid << 6) >= nrel) continue;   // whole-warp tail skip
            const float4 rv = relSD4[(ibase >> 1) + t]; // zero-pad covers overhang
            const float Ei0 = rv.x, di0 = rv.y;
            const float Ei1 = rv.z, di1 = rv.w;

            float a0 = 0.0f, a1 = 0.0f, a2 = 0.0f, a3 = 0.0f;
            #pragma unroll 8
            for (int k = 0; k < TRIPS; k++) {            // TRIPS = 64, compile-time
                const float4 n = nj4[k];                 // LDS.128 broadcast, imm offset
                a0 = fmaf(fabsf(di0 - n.y), __log2f(fmaf(n.x, Ei0, 1.0f)), a0);
                a1 = fmaf(fabsf(di1 - n.y), __log2f(fmaf(n.x, Ei1, 1.0f)), a1);
                a2 = fmaf(fabsf(di0 - n.w), __log2f(fmaf(n.z, Ei0, 1.0f)), a2);
                a3 = fmaf(fabsf(di1 - n.w), __log2f(fmaf(n.z, Ei1, 1.0f)), a3);
            }
            thread_sum += (a0 + a1) + (a2 + a3);
        }
        thread_sum *= norm;
    }

    // ---- Deterministic block reduction ----
    {
        float ws = thread_sum;
        #pragma unroll
        for (int o = 16; o > 0; o >>= 1) ws += __shfl_down_sync(0xffffffffu, ws, o);
        if (lane == 0) red_f[wid] = ws;
        __syncthreads();
        if (wid == 0) {
            float v2 = (lane < NWARP) ? red_f[lane] : 0.0f;
            #pragma unroll
            for (int o = 4; o > 0; o >>= 1) v2 += __shfl_down_sync(0xffffffffu, v2, o);
            if (lane == 0) {
                g_partial[blockIdx.x] = v2;
                g_count[blockIdx.x]   = blk_count;
            }
        }
    }

    // ---- Fused finalize: last block reduces all partials in fixed order ----
    __threadfence();
    if (t == 0)
        s_last = (atomicAdd(&g_ticket, 1u) == (unsigned)(NBLK - 1));
    __syncthreads();

    if (s_last) {
        float fs = 0.0f;
        int   cs = 0;
        for (int idx = t; idx < NBLK; idx += BDIM) {
            fs += g_partial[idx];
            cs += g_count[idx];
        }
        #pragma unroll
        for (int o = 16; o > 0; o >>= 1) {
            fs += __shfl_down_sync(0xffffffffu, fs, o);
            cs += __shfl_down_sync(0xffffffffu, cs, o);
        }
        if (lane == 0) { red_f[wid] = fs; red_i[wid] = cs; }
        __syncthreads();
        if (t == 0) {
            float st = 0.0f; int ct = 0;
            #pragma unroll
            for (int w = 0; w < NWARP; w++) { st += red_f[w]; ct += red_i[w]; }
            out[0] = (ct > 0) ? (st / (float)ct) : 0.0f;
            g_ticket = 0;   // reset for next graph replay
        }
    }
}

extern "C" void kernel_launch(void* const* d_in, const int* in_sizes, int n_in,
                              void* d_out, int out_size)
{
    const float* scores = (const float*)d_in[0];
    const int*   rels   = (const int*)d_in[1];
    (void)in_sizes; (void)n_in; (void)out_size;

    lambdarank_fused<<<NBLK, BDIM>>>(scores, rels, (float*)d_out);
}

// round 12
// speedup vs baseline: 1.4163x; 1.4163x over previous
#include <cuda_runtime.h>

#define N_POS   1024
#define BDIM    512
#define SPLIT   4
#define NBLK    (64 * SPLIT)   // 256
#define KTOP    10
#define NWARP   (BDIM / 32)    // 16
#define LSIZE   (N_POS + 64)   // float2 list capacity incl. zero pad
#define GCAP    528            // j-group capacity (512 real + pad)

__device__ float    g_partial[NBLK];
__device__ int      g_count[NBLK];
__device__ unsigned g_ticket;   // zero-init; reset to 0 by the last block each launch

__constant__ float c_idcg[11] = {
    0.0f, 1.0f, 1.6309297535714574f, 2.1309297535714574f,
    2.5616063116448505f, 2.9484591188793920f, 3.3046663059874144f,
    3.6379996393207477f, 3.9534645161064764f, 4.2544945117704580f,
    4.5435593380883460f
};

__global__ __launch_bounds__(BDIM, 2) void lambdarank_fused(
    const float* __restrict__ scores, const int* __restrict__ rels,
    float* __restrict__ out)
{
    __shared__ float2 relSD[LSIZE];   // (e^{-si}, disc_i), zero-padded tail
    __shared__ float2 nonSD[LSIZE];   // (e^{+sj}, disc_j), zero-padded tail
    __shared__ float4 grpS[GCAP];     // per j-pair: (s=E1+E2, dbar, q=E1*E2, 0)
    __shared__ int    sh_cntR[NWARP];
    __shared__ int    sh_baseR[NWARP], sh_baseN[NWARP];
    __shared__ int    sh_tot[2];
    __shared__ float  red_f[NWARP];
    __shared__ int    red_i[NWARP];
    __shared__ bool   s_last;

    const int b    = blockIdx.x >> 2;          // SPLIT = 4
    const int s    = blockIdx.x & (SPLIT - 1);
    const int t    = threadIdx.x;
    const int lane = t & 31;
    const int wid  = t >> 5;
    const unsigned lt_mask = (1u << lane) - 1u;

    // ---- Parallel deterministic stable compaction (16 warps, 64 pos each) ----
    unsigned masks[2];
    float    sc[2];
    {
        int cr = 0;
        #pragma unroll
        for (int it = 0; it < 2; it++) {
            int p = (wid << 6) + (it << 5) + lane;
            sc[it] = scores[b * N_POS + p];
            int r  = rels[b * N_POS + p];
            unsigned m = __ballot_sync(0xffffffffu, r != 0);
            masks[it] = m;
            cr += __popc(m);
        }
        if (lane == 0) sh_cntR[wid] = cr;
    }
    __syncthreads();
    if (t == 0) {
        int aR = 0, aN = 0;
        #pragma unroll
        for (int w = 0; w < NWARP; w++) {
            sh_baseR[w] = aR; sh_baseN[w] = aN;
            aR += sh_cntR[w]; aN += 64 - sh_cntR[w];
        }
        sh_tot[0] = aR; sh_tot[1] = aN;
    }
    __syncthreads();

    const int nrel = sh_tot[0];
    const int nnon = sh_tot[1];

    {
        int rb = sh_baseR[wid], nb = sh_baseN[wid];
        #pragma unroll
        for (int it = 0; it < 2; it++) {
            int p = (wid << 6) + (it << 5) + lane;
            unsigned m = masks[it];
            bool hit = (m >> lane) & 1u;
            float E  = __expf(hit ? -sc[it] : sc[it]);
            float d  = __fdividef(1.0f, __log2f((float)p + 2.0f));  // DCG discount
            float2 v = make_float2(E, d);
            int preR = __popc(m & lt_mask);
            if (hit) relSD[rb + preR]          = v;
            else     nonSD[nb + (lane - preR)] = v;
            rb += __popc(m);
            nb += 32 - __popc(m);
        }
    }

    // Zero-fill tails: E=0 entries contribute exactly 0
    for (int idx = nrel + t; idx < LSIZE; idx += BDIM)
        relSD[idx] = make_float2(0.0f, 0.0f);
    for (int idx = nnon + t; idx < LSIZE; idx += BDIM)
        nonSD[idx] = make_float2(0.0f, 0.0f);
    __syncthreads();

    // ---- Build merged j-groups: one LG2 will cover 2 j's ----
    // group k = (j=2k, j=2k+1). For an odd tail, duplicate the real disc so the
    // merged weight is exact; fully-pad groups are (0,0,0) => u=1 => lg2=0.
    for (int k = t; k < GCAP; k += BDIM) {
        float2 ja = nonSD[2 * k < LSIZE ? 2 * k : LSIZE - 1];
        float2 jb = nonSD[2 * k + 1 < LSIZE ? 2 * k + 1 : LSIZE - 1];
        if (2 * k >= LSIZE - 1) { ja = make_float2(0.f, 0.f); jb = ja; }
        float db = (2 * k + 1 >= nnon) ? ((2 * k < nnon) ? ja.y : 0.0f) : jb.y;
        grpS[k] = make_float4(ja.x + jb.x, 0.5f * (ja.y + db), ja.x * jb.x, 0.0f);
    }
    __syncthreads();

    float thread_sum = 0.0f;
    int   blk_count  = 0;

    if (nrel > 0 && nnon > 0) {
        const float idcg = c_idcg[(nrel < KTOP) ? nrel : KTOP];
        const float norm = 0.69314718055994531f / (idcg + 1e-8f);  // ln2/(idcg+eps)

        // Split REAL j-groups across the 4 blocks; round share to multiple of 4.
        const int gcnt   = (nnon + 1) >> 1;
        const int gchunk = ((((gcnt + SPLIT - 1) >> 2) + 3) & ~3);
        const int g0     = s * gchunk;

        // exact real-pair count in this block's group range
        int cj = nnon - 2 * g0;
        cj = (cj < 0) ? 0 : ((cj > 2 * gchunk) ? 2 * gchunk : cj);
        blk_count = nrel * cj;

        const float4* gj = &grpS[g0];

        for (int ibase = 0; ibase < nrel; ibase += BDIM) {
            if (ibase + (wid << 5) >= nrel) continue;   // whole-warp tail skip
            const float2 rv = relSD[ibase + t];         // zero-pad covers overhang
            const float Ei = rv.x, di = rv.y;

            float a0 = 0.0f, a1 = 0.0f, a2 = 0.0f, a3 = 0.0f;
            for (int k = 0; k < gchunk; k += 4) {       // gchunk multiple of 4
                const float4 q0 = gj[k];
                const float4 q1 = gj[k + 1];
                const float4 q2 = gj[k + 2];
                const float4 q3 = gj[k + 3];
                // u1*u2 = 1 + s*Ei + q*Ei^2 ; weight = |di - dbar|
                float u0 = fmaf(fmaf(q0.z, Ei, q0.x), Ei, 1.0f);
                float u1 = fmaf(fmaf(q1.z, Ei, q1.x), Ei, 1.0f);
                float u2 = fmaf(fmaf(q2.z, Ei, q2.x), Ei, 1.0f);
                float u3 = fmaf(fmaf(q3.z, Ei, q3.x), Ei, 1.0f);
                a0 = fmaf(fabsf(di - q0.y), __log2f(u0), a0);
                a1 = fmaf(fabsf(di - q1.y), __log2f(u1), a1);
                a2 = fmaf(fabsf(di - q2.y), __log2f(u2), a2);
                a3 = fmaf(fabsf(di - q3.y), __log2f(u3), a3);
            }
            thread_sum += (a0 + a1) + (a2 + a3);
        }
        thread_sum *= norm;
    }

    // ---- Deterministic block reduction (16 warps) ----
    {
        float ws = thread_sum;
        #pragma unroll
        for (int o = 16; o > 0; o >>= 1) ws += __shfl_down_sync(0xffffffffu, ws, o);
        if (lane == 0) red_f[wid] = ws;
        __syncthreads();
        if (wid == 0) {
            float v2 = (lane < NWARP) ? red_f[lane] : 0.0f;
            #pragma unroll
            for (int o = 8; o > 0; o >>= 1) v2 += __shfl_down_sync(0xffffffffu, v2, o);
            if (lane == 0) {
                g_partial[blockIdx.x] = v2;
                g_count[blockIdx.x]   = blk_count;
            }
        }
    }

    // ---- Fused finalize: last block reduces all partials in fixed order ----
    __threadfence();
    if (t == 0)
        s_last = (atomicAdd(&g_ticket, 1u) == (unsigned)(NBLK - 1));
    __syncthreads();

    if (s_last) {
        float fs = 0.0f;
        int   cs = 0;
        if (t < NBLK) {                      // NBLK = 256 < BDIM = 512
            fs = g_partial[t];
            cs = g_count[t];
        }
        #pragma unroll
        for (int o = 16; o > 0; o >>= 1) {
            fs += __shfl_down_sync(0xffffffffu, fs, o);
            cs += __shfl_down_sync(0xffffffffu, cs, o);
        }
        if (lane == 0) { red_f[wid] = fs; red_i[wid] = cs; }
        __syncthreads();
        if (t == 0) {
            float st = 0.0f; int ct = 0;
            #pragma unroll
            for (int w = 0; w < NWARP; w++) { st += red_f[w]; ct += red_i[w]; }
            out[0] = (ct > 0) ? (st / (float)ct) : 0.0f;
            g_ticket = 0;   // reset for next graph replay
        }
    }
}

extern "C" void kernel_launch(void* const* d_in, const int* in_sizes, int n_in,
                              void* d_out, int out_size)
{
    const float* scores = (const float*)d_in[0];
    const int*   rels   = (const int*)d_in[1];
    (void)in_sizes; (void)n_in; (void)out_size;

    lambdarank_fused<<<NBLK, BDIM>>>(scores, rels, (float*)d_out);
}

// round 13
// speedup vs baseline: 1.4800x; 1.0450x over previous
#include <cuda_runtime.h>

#define N_POS   1024
#define BDIM    512
#define SPLIT   4
#define NBLK    (64 * SPLIT)   // 256
#define KTOP    10
#define NWARP   (BDIM / 32)    // 16
#define LSIZE   (N_POS + 64)   // 1088 float2 entries (zero pad)
#define GCAP    544            // j-group capacity (covers 4*gchunk worst case)

__device__ float    g_partial[NBLK];
__device__ int      g_count[NBLK];
__device__ unsigned g_ticket;   // zero-init; reset to 0 by the last block each launch

__constant__ float c_idcg[11] = {
    0.0f, 1.0f, 1.6309297535714574f, 2.1309297535714574f,
    2.5616063116448505f, 2.9484591188793920f, 3.3046663059874144f,
    3.6379996393207477f, 3.9534645161064764f, 4.2544945117704580f,
    4.5435593380883460f
};

__global__ __launch_bounds__(BDIM, 2) void lambdarank_fused(
    const float* __restrict__ scores, const int* __restrict__ rels,
    float* __restrict__ out)
{
    __shared__ float4 relSD4[LSIZE / 2];  // (E,d) pairs; float4 = one i-pair
    __shared__ float2 nonSD[LSIZE];       // (e^{+sj}, disc_j), zero-padded
    __shared__ float4 grpS[GCAP];         // j-group: (s=E1+E2, dbar, q=E1*E2, 0)
    __shared__ int    sh_cntR[NWARP];
    __shared__ int    sh_baseR[NWARP], sh_baseN[NWARP];
    __shared__ int    sh_tot[2];
    __shared__ float  red_f[NWARP];
    __shared__ int    red_i[NWARP];
    __shared__ bool   s_last;

    float2* relSD = (float2*)relSD4;

    const int b    = blockIdx.x >> 2;          // SPLIT = 4
    const int s    = blockIdx.x & (SPLIT - 1);
    const int t    = threadIdx.x;
    const int lane = t & 31;
    const int wid  = t >> 5;
    const unsigned lt_mask = (1u << lane) - 1u;

    // ---- Parallel deterministic stable compaction (16 warps, 64 pos each) ----
    unsigned masks[2];
    float    sc[2];
    {
        int cr = 0;
        #pragma unroll
        for (int it = 0; it < 2; it++) {
            int p = (wid << 6) + (it << 5) + lane;
            sc[it] = scores[b * N_POS + p];
            int r  = rels[b * N_POS + p];
            unsigned m = __ballot_sync(0xffffffffu, r != 0);
            masks[it] = m;
            cr += __popc(m);
        }
        if (lane == 0) sh_cntR[wid] = cr;
    }
    __syncthreads();
    if (t == 0) {
        int aR = 0, aN = 0;
        #pragma unroll
        for (int w = 0; w < NWARP; w++) {
            sh_baseR[w] = aR; sh_baseN[w] = aN;
            aR += sh_cntR[w]; aN += 64 - sh_cntR[w];
        }
        sh_tot[0] = aR; sh_tot[1] = aN;
    }
    __syncthreads();

    const int nrel = sh_tot[0];
    const int nnon = sh_tot[1];

    {
        int rb = sh_baseR[wid], nb = sh_baseN[wid];
        #pragma unroll
        for (int it = 0; it < 2; it++) {
            int p = (wid << 6) + (it << 5) + lane;
            unsigned m = masks[it];
            bool hit = (m >> lane) & 1u;
            float E  = __expf(hit ? -sc[it] : sc[it]);
            float d  = __fdividef(1.0f, __log2f((float)p + 2.0f));  // DCG discount
            float2 v = make_float2(E, d);
            int preR = __popc(m & lt_mask);
            if (hit) relSD[rb + preR]          = v;
            else     nonSD[nb + (lane - preR)] = v;
            rb += __popc(m);
            nb += 32 - __popc(m);
        }
    }

    // Zero-fill tails: E=0 entries contribute exactly 0
    for (int idx = nrel + t; idx < LSIZE; idx += BDIM)
        relSD[idx] = make_float2(0.0f, 0.0f);
    for (int idx = nnon + t; idx < LSIZE; idx += BDIM)
        nonSD[idx] = make_float2(0.0f, 0.0f);
    __syncthreads();

    // Odd nrel: duplicate last rel disc with E=0 so the i-pair's mean disc is
    // exact for the real i (u contribution of pad = 1).
    if (t == 0 && (nrel & 1))
        relSD[nrel] = make_float2(0.0f, relSD[nrel - 1].y);

    // ---- Build merged j-groups (2 j's each) ----
    for (int k = t; k < GCAP; k += BDIM) {
        float2 ja = nonSD[2 * k];
        float2 jb = nonSD[2 * k + 1];
        float db = (2 * k + 1 >= nnon) ? ((2 * k < nnon) ? ja.y : 0.0f) : jb.y;
        grpS[k] = make_float4(ja.x + jb.x, 0.5f * (ja.y + db), ja.x * jb.x, 0.0f);
    }
    __syncthreads();

    float thread_sum = 0.0f;
    int   blk_count  = 0;

    if (nrel > 0 && nnon > 0) {
        const float idcg = c_idcg[(nrel < KTOP) ? nrel : KTOP];
        const float norm = 0.69314718055994531f / (idcg + 1e-8f);  // ln2/(idcg+eps)

        // j-groups for this block (chunk multiple of 8), then split in halves
        // across the two warp-groups (warps 0-7 vs 8-15).
        const int gcnt   = (nnon + 1) >> 1;
        const int gchunk = ((((gcnt + SPLIT - 1) >> 2) + 7) & ~7);
        const int g0b    = s * gchunk;

        int cj = nnon - 2 * g0b;                       // exact real pairs in block range
        cj = (cj < 0) ? 0 : ((cj > 2 * gchunk) ? 2 * gchunk : cj);
        blk_count = nrel * cj;

        const int  half = gchunk >> 1;                 // multiple of 4
        const int  jh   = wid >> 3;                    // 0 or 1
        const float4* gj = &grpS[g0b + jh * half];

        // i-pairs: thread handles pair p = (wid&7)*32 + lane, stride 256
        const int npairs = (nrel + 1) >> 1;
        for (int p = ((wid & 7) << 5) + lane; p < npairs; p += 256) {
            const float4 rv = relSD4[p];
            const float Ei0 = rv.x, Ei1 = rv.z;
            const float dbi = 0.5f * (rv.y + rv.w);    // exact when odd-dup applied

            float a0 = 0.0f, a1 = 0.0f, a2 = 0.0f, a3 = 0.0f;
            for (int k = 0; k < half; k += 4) {
                const float4 q0 = gj[k];
                const float4 q1 = gj[k + 1];
                const float4 q2 = gj[k + 2];
                const float4 q3 = gj[k + 3];
                // P(x) = 1 + (q*x + s)*x ; U = P(Ei0)*P(Ei1) covers 4 pairs
                float uA0 = fmaf(fmaf(q0.z, Ei0, q0.x), Ei0, 1.0f);
                float uB0 = fmaf(fmaf(q0.z, Ei1, q0.x), Ei1, 1.0f);
                float uA1 = fmaf(fmaf(q1.z, Ei0, q1.x), Ei0, 1.0f);
                float uB1 = fmaf(fmaf(q1.z, Ei1, q1.x), Ei1, 1.0f);
                float uA2 = fmaf(fmaf(q2.z, Ei0, q2.x), Ei0, 1.0f);
                float uB2 = fmaf(fmaf(q2.z, Ei1, q2.x), Ei1, 1.0f);
                float uA3 = fmaf(fmaf(q3.z, Ei0, q3.x), Ei0, 1.0f);
                float uB3 = fmaf(fmaf(q3.z, Ei1, q3.x), Ei1, 1.0f);
                a0 = fmaf(fabsf(dbi - q0.y), __log2f(uA0 * uB0), a0);
                a1 = fmaf(fabsf(dbi - q1.y), __log2f(uA1 * uB1), a1);
                a2 = fmaf(fabsf(dbi - q2.y), __log2f(uA2 * uB2), a2);
                a3 = fmaf(fabsf(dbi - q3.y), __log2f(uA3 * uB3), a3);
            }
            thread_sum += (a0 + a1) + (a2 + a3);
        }
        thread_sum *= norm;
    }

    // ---- Deterministic block reduction (16 warps) ----
    {
        float ws = thread_sum;
        #pragma unroll
        for (int o = 16; o > 0; o >>= 1) ws += __shfl_down_sync(0xffffffffu, ws, o);
        if (lane == 0) red_f[wid] = ws;
        __syncthreads();
        if (wid == 0) {
            float v2 = (lane < NWARP) ? red_f[lane] : 0.0f;
            #pragma unroll
            for (int o = 8; o > 0; o >>= 1) v2 += __shfl_down_sync(0xffffffffu, v2, o);
            if (lane == 0) {
                g_partial[blockIdx.x] = v2;
                g_count[blockIdx.x]   = blk_count;
            }
        }
    }

    // ---- Fused finalize: last block reduces all partials in fixed order ----
    __threadfence();
    if (t == 0)
        s_last = (atomicAdd(&g_ticket, 1u) == (unsigned)(NBLK - 1));
    __syncthreads();

    if (s_last) {
        float fs = 0.0f;
        int   cs = 0;
        if (t < NBLK) {                      // NBLK = 256 < BDIM = 512
            fs = g_partial[t];
            cs = g_count[t];
        }
        #pragma unroll
        for (int o = 16; o > 0; o >>= 1) {
            fs += __shfl_down_sync(0xffffffffu, fs, o);
            cs += __shfl_down_sync(0xffffffffu, cs, o);
        }
        if (lane == 0) { red_f[wid] = fs; red_i[wid] = cs; }
        __syncthreads();
        if (t == 0) {
            float st = 0.0f; int ct = 0;
            #pragma unroll
            for (int w = 0; w < NWARP; w++) { st += red_f[w]; ct += red_i[w]; }
            out[0] = (ct > 0) ? (st / (float)ct) : 0.0f;
            g_ticket = 0;   // reset for next graph replay
        }
    }
}

extern "C" void kernel_launch(void* const* d_in, const int* in_sizes, int n_in,
                              void* d_out, int out_size)
{
    const float* scores = (const float*)d_in[0];
    const int*   rels   = (const int*)d_in[1];
    (void)in_sizes; (void)n_in; (void)out_size;

    lambdarank_fused<<<NBLK, BDIM>>>(scores, rels, (float*)d_out);
}

// round 15
// speedup vs baseline: 1.4912x; 1.0076x over previous
#include <cuda_runtime.h>

#define N_POS   1024
#define BDIM    512
#define SPLIT   4
#define NBLK    (64 * SPLIT)   // 256
#define KTOP    10
#define NWARP   (BDIM / 32)    // 16
#define LSIZE   (N_POS + 64)   // 1088 float2 entries (zero pad)
#define GCAP    544            // j-group capacity (2 j's each)

__device__ float    g_partial[NBLK];
__device__ int      g_count[NBLK];
__device__ unsigned g_ticket;   // zero-init; reset to 0 by the last block each launch

__constant__ float c_idcg[11] = {
    0.0f, 1.0f, 1.6309297535714574f, 2.1309297535714574f,
    2.5616063116448505f, 2.9484591188793920f, 3.3046663059874144f,
    3.6379996393207477f, 3.9534645161064764f, 4.2544945117704580f,
    4.5435593380883460f
};

__global__ __launch_bounds__(BDIM, 2) void lambdarank_fused(
    const float* __restrict__ scores, const int* __restrict__ rels,
    float* __restrict__ out)
{
    __shared__ float4 relSD4[LSIZE / 2];  // (E,d) pairs; float4 = one i-pair
    __shared__ float2 nonSD[LSIZE];       // (e^{+sj}, disc_j), zero-padded
    __shared__ float4 grpS[GCAP];         // j-group: (s=E1+E2, dbar, q=E1*E2, 0)
    __shared__ int    sh_cntR[NWARP];
    __shared__ int    sh_baseR[NWARP];
    __shared__ int    sh_nrel;
    __shared__ float  red_f[NWARP];
    __shared__ int    red_i[NWARP];
    __shared__ bool   s_last;

    float2* relSD = (float2*)relSD4;

    const int b    = blockIdx.x >> 2;          // SPLIT = 4
    const int s    = blockIdx.x & (SPLIT - 1);
    const int t    = threadIdx.x;
    const int lane = t & 31;
    const int wid  = t >> 5;
    const unsigned lt_mask = (1u << lane) - 1u;

    // ---- Ballot count (16 warps, 64 positions each) ----
    unsigned masks[2];
    float    sc[2];
    {
        int cr = 0;
        #pragma unroll
        for (int it = 0; it < 2; it++) {
            int p = (wid << 6) + (it << 5) + lane;
            sc[it] = scores[b * N_POS + p];
            int r  = rels[b * N_POS + p];
            unsigned m = __ballot_sync(0xffffffffu, r != 0);
            masks[it] = m;
            cr += __popc(m);
        }
        if (lane == 0) sh_cntR[wid] = cr;
    }
    __syncthreads();

    // ---- Parallel exclusive scan of per-warp counts (warp 0) ----
    if (wid == 0) {
        int v = (lane < NWARP) ? sh_cntR[lane] : 0;
        int incl = v;
        #pragma unroll
        for (int o = 1; o < NWARP; o <<= 1) {
            int u = __shfl_up_sync(0xffffffffu, incl, o);
            if (lane >= o) incl += u;
        }
        if (lane < NWARP) {
            sh_baseR[lane] = incl - v;
            if (lane == NWARP - 1) sh_nrel = incl;
        }
    }
    __syncthreads();

    const int nrel = sh_nrel;
    const int nnon = N_POS - nrel;    // binary relevance: complement

    // ---- Deterministic stable scatter ----
    {
        int rb = sh_baseR[wid];
        int nb = (wid << 6) - rb;     // baseN = 64*wid - baseR
        #pragma unroll
        for (int it = 0; it < 2; it++) {
            int p = (wid << 6) + (it << 5) + lane;
            unsigned m = masks[it];
            bool hit = (m >> lane) & 1u;
            float E  = __expf(hit ? -sc[it] : sc[it]);
            float d  = __fdividef(1.0f, __log2f((float)p + 2.0f));  // DCG discount
            float2 v = make_float2(E, d);
            int preR = __popc(m & lt_mask);
            if (hit) relSD[rb + preR]          = v;
            else     nonSD[nb + (lane - preR)] = v;
            rb += __popc(m);
            nb += 32 - __popc(m);
        }
    }

    // Zero-fill tails (disjoint from scatter writes): E=0 contributes exactly 0
    for (int idx = nrel + t; idx < LSIZE; idx += BDIM)
        relSD[idx] = make_float2(0.0f, 0.0f);
    for (int idx = nnon + t; idx < LSIZE; idx += BDIM)
        nonSD[idx] = make_float2(0.0f, 0.0f);
    __syncthreads();

    // Odd nrel: duplicate last rel disc with E=0 so i-pair mean disc is exact
    if (t == 0 && (nrel & 1))
        relSD[nrel] = make_float2(0.0f, relSD[nrel - 1].y);

    // ---- Build merged j-groups (2 j's each): one LG2 covers 4 pairs ----
    for (int k = t; k < GCAP; k += BDIM) {
        float2 ja = nonSD[2 * k];
        float2 jb = nonSD[2 * k + 1];
        float db = (2 * k + 1 >= nnon) ? ((2 * k < nnon) ? ja.y : 0.0f) : jb.y;
        grpS[k] = make_float4(ja.x + jb.x, 0.5f * (ja.y + db), ja.x * jb.x, 0.0f);
    }
    __syncthreads();

    float thread_sum = 0.0f;

    if (nrel > 0 && nnon > 0) {
        const float idcg = c_idcg[(nrel < KTOP) ? nrel : KTOP];
        const float norm = 0.69314718055994531f / (idcg + 1e-8f);  // ln2/(idcg+eps)

        // j-groups for this block (chunk multiple of 8), split in halves
        // across the two warp-groups (warps 0-7 vs 8-15).
        const int gcnt   = (nnon + 1) >> 1;
        const int gchunk = ((((gcnt + SPLIT - 1) >> 2) + 7) & ~7);
        const int g0b    = s * gchunk;

        const int  half = gchunk >> 1;                 // multiple of 4
        const int  jh   = wid >> 3;                    // warp-group: 0 or 1
        const float4* gj = &grpS[g0b + jh * half];

        // i-pairs: thread handles pair p = (wid&7)*32 + lane, stride 256
        const int npairs = (nrel + 1) >> 1;
        for (int p = ((wid & 7) << 5) + lane; p < npairs; p += 256) {
            const float4 rv = relSD4[p];
            const float Ei0 = rv.x, Ei1 = rv.z;
            const float dbi = 0.5f * (rv.y + rv.w);

            float a0 = 0.0f, a1 = 0.0f, a2 = 0.0f, a3 = 0.0f;
            for (int k = 0; k < half; k += 4) {
                const float4 q0 = gj[k];
                const float4 q1 = gj[k + 1];
                const float4 q2 = gj[k + 2];
                const float4 q3 = gj[k + 3];
                // P(x) = 1 + (q*x + s)*x ; U = P(Ei0)*P(Ei1) covers 4 pairs
                float uA0 = fmaf(fmaf(q0.z, Ei0, q0.x), Ei0, 1.0f);
                float uB0 = fmaf(fmaf(q0.z, Ei1, q0.x), Ei1, 1.0f);
                float uA1 = fmaf(fmaf(q1.z, Ei0, q1.x), Ei0, 1.0f);
                float uB1 = fmaf(fmaf(q1.z, Ei1, q1.x), Ei1, 1.0f);
                float uA2 = fmaf(fmaf(q2.z, Ei0, q2.x), Ei0, 1.0f);
                float uB2 = fmaf(fmaf(q2.z, Ei1, q2.x), Ei1, 1.0f);
                float uA3 = fmaf(fmaf(q3.z, Ei0, q3.x), Ei0, 1.0f);
                float uB3 = fmaf(fmaf(q3.z, Ei1, q3.x), Ei1, 1.0f);
                a0 = fmaf(fabsf(dbi - q0.y), __log2f(uA0 * uB0), a0);
                a1 = fmaf(fabsf(dbi - q1.y), __log2f(uA1 * uB1), a1);
                a2 = fmaf(fabsf(dbi - q2.y), __log2f(uA2 * uB2), a2);
                a3 = fmaf(fabsf(dbi - q3.y), __log2f(uA3 * uB3), a3);
            }
            thread_sum += (a0 + a1) + (a2 + a3);
        }
        thread_sum *= norm;
    }

    // ---- Deterministic block reduction (16 warps) ----
    {
        float ws = thread_sum;
        #pragma unroll
        for (int o = 16; o > 0; o >>= 1) ws += __shfl_down_sync(0xffffffffu, ws, o);
        if (lane == 0) red_f[wid] = ws;
        __syncthreads();
        if (wid == 0) {
            float v2 = (lane < NWARP) ? red_f[lane] : 0.0f;
            #pragma unroll
            for (int o = 8; o > 0; o >>= 1) v2 += __shfl_down_sync(0xffffffffu, v2, o);
            if (lane == 0) {
                g_partial[blockIdx.x] = v2;
                // Exact per-batch pair count, written once per batch (s == 0)
                g_count[blockIdx.x] = (s == 0) ? nrel * nnon : 0;
            }
        }
    }

    // ---- Fused finalize: last block reduces all partials in fixed order ----
    __threadfence();
    if (t == 0)
        s_last = (atomicAdd(&g_ticket, 1u) == (unsigned)(NBLK - 1));
    __syncthreads();

    if (s_last) {
        float fs = 0.0f;
        int   cs = 0;
        if (t < NBLK) {                      // NBLK = 256 < BDIM = 512
            fs = g_partial[t];
            cs = g_count[t];
        }
        #pragma unroll
        for (int o = 16; o > 0; o >>= 1) {
            fs += __shfl_down_sync(0xffffffffu, fs, o);
            cs += __shfl_down_sync(0xffffffffu, cs, o);
        }
        if (lane == 0) { red_f[wid] = fs; red_i[wid] = cs; }
        __syncthreads();
        if (t == 0) {
            float st = 0.0f; int ct = 0;
            #pragma unroll
            for (int w = 0; w < NWARP; w++) { st += red_f[w]; ct += red_i[w]; }
            out[0] = (ct > 0) ? (st / (float)ct) : 0.0f;
            g_ticket = 0;   // reset for next graph replay
        }
    }
}

extern "C" void kernel_launch(void* const* d_in, const int* in_sizes, int n_in,
                              void* d_out, int out_size)
{
    const float* scores = (const float*)d_in[0];
    const int*   rels   = (const int*)d_in[1];
    (void)in_sizes; (void)n_in; (void)out_size;

    lambdarank_fused<<<NBLK, BDIM>>>(scores, rels, (float*)d_out);
}